// round 1
// baseline (speedup 1.0000x reference)
#include <cuda_runtime.h>
#include <cuda_bf16.h>
#include <cstdint>

// Problem constants
#define BATCH   16
#define C_IN    64
#define C_OUT   128
#define HH      128
#define WW      128

// Tiling
#define OC_TILE 32     // out channels per block
#define TH      8      // output rows per block
#define TW      32     // output cols per block
#define IC_CHUNK 16    // input channels per smem stage
#define XROW    36     // padded smem row stride (floats), 16B aligned; 34 valid cols

typedef unsigned long long u64;

// Dense-repacked weights: [ic=64][tap=9][oc=128]  (oc contiguous -> aligned oc pairs)
__device__ float g_wdense[C_IN * 9 * C_OUT];

__device__ __forceinline__ void fma2(u64& d, u64 a, u64 b) {
    asm("fma.rn.f32x2 %0, %1, %2, %0;" : "+l"(d) : "l"(a), "l"(b));
}
__device__ __forceinline__ u64 pack2(float lo, float hi) {
    u64 r; asm("mov.b64 %0, {%1, %2};" : "=l"(r) : "f"(lo), "f"(hi)); return r;
}
__device__ __forceinline__ void unpack2(float& lo, float& hi, u64 v) {
    asm("mov.b64 {%0, %1}, %2;" : "=f"(lo), "=f"(hi) : "l"(v));
}

// weight src dims: (i=16, j=8, p=8, q=8, kh=3, kw=3); dense oc=i*8+p, ic=j*8+q
__global__ void repack_weights_kernel(const float* __restrict__ w) {
    int idx = blockIdx.x * 256 + threadIdx.x;
    if (idx >= C_IN * 9 * C_OUT) return;
    int oc = idx & 127;
    int t  = (idx >> 7) % 9;
    int ic = (idx >> 7) / 9;
    int i = oc >> 3, p = oc & 7;
    int j = ic >> 3, q = ic & 7;
    int kh = t / 3, kw = t % 3;
    g_wdense[idx] = w[i * 4608 + j * 576 + p * 72 + q * 9 + kh * 3 + kw];
}

__global__ __launch_bounds__(256, 3)
void oct_conv_kernel(const float* __restrict__ x,
                     const float* __restrict__ bias,
                     float* __restrict__ out) {
    __shared__ __align__(16) float x_s[IC_CHUNK][TH + 2][XROW];
    __shared__ __align__(16) float w_s[IC_CHUNK][9][OC_TILE];

    const int tid  = threadIdx.x;
    const int warp = tid >> 5;        // 0..7 : oc group (4 oc each)
    const int lane = tid & 31;
    const int th   = lane >> 2;       // 0..7 : output row in tile
    const int cg   = lane & 3;        // 0..3 : column group (8 px each)

    const int tw_idx = blockIdx.x & 3;
    const int th_idx = blockIdx.x >> 2;
    const int ob = blockIdx.y;        // 0..3 : oc block of 32
    const int b  = blockIdx.z;        // batch

    const int h0  = th_idx * TH;
    const int w0c = tw_idx * TW;

    u64 acc[2][8];
    #pragma unroll
    for (int pr = 0; pr < 2; ++pr)
        #pragma unroll
        for (int px = 0; px < 8; ++px) acc[pr][px] = 0ull;

    for (int ic0 = 0; ic0 < C_IN; ic0 += IC_CHUNK) {
        // ---- stage input tile (with halo, zero-padded at image edges) ----
        for (int j = tid; j < IC_CHUNK * (TH + 2) * 34; j += 256) {
            int c   = j % 34;
            int t2  = j / 34;
            int r   = t2 % (TH + 2);
            int icl = t2 / (TH + 2);
            int gh = h0 - 1 + r;
            int gw = w0c - 1 + c;
            float v = 0.0f;
            if ((unsigned)gh < HH && (unsigned)gw < WW)
                v = x[(((b * C_IN) + ic0 + icl) * HH + gh) * WW + gw];
            x_s[icl][r][c] = v;
        }
        // ---- stage weights for this (ic chunk, oc block) ----
        for (int j = tid; j < IC_CHUNK * 9 * OC_TILE; j += 256) {
            int ocl = j & (OC_TILE - 1);
            int t2  = j >> 5;
            int t   = t2 % 9;
            int icl = t2 / 9;
            w_s[icl][t][ocl] = g_wdense[((ic0 + icl) * 9 + t) * C_OUT + ob * OC_TILE + ocl];
        }
        __syncthreads();

        // ---- compute ----
        for (int icl = 0; icl < IC_CHUNK; ++icl) {
            #pragma unroll
            for (int kh = 0; kh < 3; ++kh) {
                const float* xrow = &x_s[icl][th + kh][cg * 8];
                // 10 consecutive input floats (16B-aligned base)
                float4 xa = *(const float4*)(xrow);
                float4 xb = *(const float4*)(xrow + 4);
                float2 xc = *(const float2*)(xrow + 8);
                u64 xs[10];
                xs[0] = pack2(xa.x, xa.x); xs[1] = pack2(xa.y, xa.y);
                xs[2] = pack2(xa.z, xa.z); xs[3] = pack2(xa.w, xa.w);
                xs[4] = pack2(xb.x, xb.x); xs[5] = pack2(xb.y, xb.y);
                xs[6] = pack2(xb.z, xb.z); xs[7] = pack2(xb.w, xb.w);
                xs[8] = pack2(xc.x, xc.x); xs[9] = pack2(xc.y, xc.y);
                #pragma unroll
                for (int kw = 0; kw < 3; ++kw) {
                    const u64* wp = (const u64*)&w_s[icl][kh * 3 + kw][warp * 4];
                    u64 w01 = wp[0];   // oc (base+0, base+1)
                    u64 w23 = wp[1];   // oc (base+2, base+3)
                    #pragma unroll
                    for (int px = 0; px < 8; ++px) {
                        fma2(acc[0][px], xs[px + kw], w01);
                        fma2(acc[1][px], xs[px + kw], w23);
                    }
                }
            }
        }
        __syncthreads();
    }

    // ---- epilogue: bias + store ----
    const int h    = h0 + th;
    const int wcol = w0c + cg * 8;
    const int ocg  = ob * OC_TILE + warp * 4;

    #pragma unroll
    for (int pr = 0; pr < 2; ++pr) {
        float lo[8], hi[8];
        #pragma unroll
        for (int px = 0; px < 8; ++px) unpack2(lo[px], hi[px], acc[pr][px]);

        const int oc0 = ocg + pr * 2;
        const float b0 = bias[oc0];
        const float b1 = bias[oc0 + 1];

        float* p0 = out + (((size_t)(b * C_OUT + oc0) * HH + h) * WW + wcol);
        float* p1 = p0 + (size_t)HH * WW;

        float4 v0a = make_float4(lo[0] + b0, lo[1] + b0, lo[2] + b0, lo[3] + b0);
        float4 v0b = make_float4(lo[4] + b0, lo[5] + b0, lo[6] + b0, lo[7] + b0);
        float4 v1a = make_float4(hi[0] + b1, hi[1] + b1, hi[2] + b1, hi[3] + b1);
        float4 v1b = make_float4(hi[4] + b1, hi[5] + b1, hi[6] + b1, hi[7] + b1);

        *(float4*)(p0)     = v0a;
        *(float4*)(p0 + 4) = v0b;
        *(float4*)(p1)     = v1a;
        *(float4*)(p1 + 4) = v1b;
    }
}

extern "C" void kernel_launch(void* const* d_in, const int* in_sizes, int n_in,
                              void* d_out, int out_size) {
    const float* x    = (const float*)d_in[0];
    const float* wgt  = (const float*)d_in[1];
    const float* bias = (const float*)d_in[2];
    float* out = (float*)d_out;

    // 1) repack weights into [ic][tap][oc] dense layout
    repack_weights_kernel<<<(C_IN * 9 * C_OUT + 255) / 256, 256>>>(wgt);

    // 2) main conv
    dim3 grid((WW / TW) * (HH / TH), C_OUT / OC_TILE, BATCH);  // (64, 4, 16)
    oct_conv_kernel<<<grid, 256>>>(x, bias, out);
}

// round 3
// speedup vs baseline: 6.1297x; 6.1297x over previous
#include <cuda_runtime.h>
#include <cuda_fp16.h>
#include <cstdint>

// ---------------- problem constants ----------------
#define BATCH   16
#define C_IN    64
#define C_OUT   128
#define HH      128
#define WW      128
#define PW      130              // padded width/height
#define PIX_PAD (PW*PW)          // 16900 padded pixels
#define XT_ROWS 16904            // + guard rows (halo overrun)
#define NTAP    9

// smem: two stages of (A 128x72 halfs + B 128x72 halfs), 144B row stride
#define ROWB      144                       // bytes per smem row (72 halfs)
#define TILE_B    (128 * ROWB)              // 18432
#define STAGE_B   (2 * TILE_B)              // 36864 (A + B)
#define SMEM_MAIN (2 * STAGE_B)             // 73728 (double buffered)
// epilogue reuses same smem as float[128][136] = 69632 B

// ---------------- device globals (scratch) ----------------
__device__ __half g_xt[(size_t)BATCH * XT_ROWS * C_IN];   // [b][pixel][ic]
__device__ __half g_wt[NTAP * C_OUT * C_IN];              // [tap][oc][ic]

// ---------------- ptx helpers ----------------
__device__ __forceinline__ uint32_t smem_u32(const void* p) {
    uint32_t a;
    asm("{ .reg .u64 t; cvta.to.shared.u64 t, %1; cvt.u32.u64 %0, t; }" : "=r"(a) : "l"(p));
    return a;
}
__device__ __forceinline__ void cp_async16(uint32_t dst, const void* src) {
    asm volatile("cp.async.cg.shared.global [%0], [%1], 16;" :: "r"(dst), "l"(src));
}
__device__ __forceinline__ void cp_commit() {
    asm volatile("cp.async.commit_group;" ::: "memory");
}
template <int N>
__device__ __forceinline__ void cp_wait() {
    asm volatile("cp.async.wait_group %0;" :: "n"(N) : "memory");
}
__device__ __forceinline__ void ldm_x4(uint32_t& r0, uint32_t& r1, uint32_t& r2, uint32_t& r3, uint32_t addr) {
    asm volatile("ldmatrix.sync.aligned.m8n8.x4.shared.b16 {%0,%1,%2,%3}, [%4];"
                 : "=r"(r0), "=r"(r1), "=r"(r2), "=r"(r3) : "r"(addr));
}
__device__ __forceinline__ void mma16816(float* c, uint32_t a0, uint32_t a1, uint32_t a2, uint32_t a3,
                                         uint32_t b0, uint32_t b1) {
    asm volatile("mma.sync.aligned.m16n8k16.row.col.f32.f16.f16.f32 "
                 "{%0,%1,%2,%3}, {%4,%5,%6,%7}, {%8,%9}, {%0,%1,%2,%3};"
                 : "+f"(c[0]), "+f"(c[1]), "+f"(c[2]), "+f"(c[3])
                 : "r"(a0), "r"(a1), "r"(a2), "r"(a3), "r"(b0), "r"(b1));
}

// ---------------- prep: weights fp32 -> fp16 [tap][oc][ic] ----------------
__global__ void prep_weights(const float* __restrict__ w) {
    int idx = blockIdx.x * 256 + threadIdx.x;
    if (idx >= NTAP * C_OUT * C_IN) return;
    int ic  = idx & 63;
    int oc  = (idx >> 6) & 127;
    int tap = idx >> 13;
    int i = oc >> 3, p = oc & 7;
    int j = ic >> 3, q = ic & 7;
    int kh = tap / 3, kw = tap % 3;
    g_wt[idx] = __float2half_rn(w[i * 4608 + j * 576 + p * 72 + q * 9 + kh * 3 + kw]);
}

// ---------------- prep: x fp32 NCHW -> padded pixel-major fp16 [b][pix][ic] ----------------
__global__ __launch_bounds__(256)
void prep_xt(const float* __restrict__ x) {
    __shared__ float buf[64][133];
    const int hp = blockIdx.x;   // 0..129
    const int b  = blockIdx.y;
    const int tid = threadIdx.x;
    __half* dst = g_xt + ((size_t)b * XT_ROWS + (size_t)hp * PW) * C_IN;

    if (hp == 0 || hp == PW - 1) {
        for (int idx = tid; idx < PW * C_IN; idx += 256) dst[idx] = __float2half_rn(0.0f);
        if (hp == PW - 1) {
            __half* g = g_xt + ((size_t)b * XT_ROWS + PIX_PAD) * C_IN;
            for (int idx = tid; idx < 4 * C_IN; idx += 256) g[idx] = __float2half_rn(0.0f);
        }
        return;
    }
    const float* src = x + ((size_t)b * C_IN * HH + (size_t)(hp - 1)) * WW;
    for (int idx = tid; idx < C_IN * 32; idx += 256) {
        int ic = idx >> 5, f4 = idx & 31;
        float4 v = *(const float4*)(src + (size_t)ic * HH * WW + f4 * 4);
        buf[ic][1 + f4 * 4 + 0] = v.x;
        buf[ic][1 + f4 * 4 + 1] = v.y;
        buf[ic][1 + f4 * 4 + 2] = v.z;
        buf[ic][1 + f4 * 4 + 3] = v.w;
    }
    __syncthreads();
    for (int idx = tid; idx < PW * C_IN; idx += 256) {
        int wp = idx >> 6, ic = idx & 63;
        float v = (wp == 0 || wp == PW - 1) ? 0.0f : buf[ic][wp];
        dst[(size_t)wp * C_IN + ic] = __float2half_rn(v);
    }
}

// ---------------- chunk loader (cp.async): one tap = 64 K ----------------
__device__ __forceinline__ void load_chunk(uint32_t sA, uint32_t sB,
                                           const __half* xtb, int tap, int tid) {
    const int shift = (tap / 3) * PW + (tap % 3);
    const __half* asrc = xtb + (size_t)shift * C_IN;
    #pragma unroll
    for (int i = 0; i < 4; ++i) {
        int idx = tid + i * 256;
        int m = idx >> 3, c = idx & 7;
        cp_async16(sA + m * ROWB + c * 16, asrc + (size_t)m * C_IN + c * 8);
    }
    const __half* bsrc = g_wt + (size_t)tap * C_OUT * C_IN;
    #pragma unroll
    for (int i = 0; i < 4; ++i) {
        int idx = tid + i * 256;
        int oc = idx >> 3, c = idx & 7;
        cp_async16(sB + oc * ROWB + c * 16, bsrc + (size_t)oc * C_IN + c * 8);
    }
    cp_commit();
}

// ---------------- main kernel ----------------
__global__ __launch_bounds__(256, 2)
void oct_mma_kernel(const float* __restrict__ bias, float* __restrict__ out) {
    extern __shared__ char smem[];
    const uint32_t sb = smem_u32(smem);
    const int tid  = threadIdx.x;
    const int wid  = tid >> 5;
    const int lane = tid & 31;
    const int mwarp = wid & 3;        // m block of 32
    const int nwarp = wid >> 2;       // n block of 64

    const int mtile = blockIdx.x;     // 0..129
    const int b     = blockIdx.y;     // 0..15
    const int m0    = mtile * 128;

    const __half* xtb = g_xt + ((size_t)b * XT_ROWS + m0) * C_IN;

    float acc[2][8][4];
    #pragma unroll
    for (int mf = 0; mf < 2; ++mf)
        #pragma unroll
        for (int nf = 0; nf < 8; ++nf)
            #pragma unroll
            for (int c = 0; c < 4; ++c) acc[mf][nf][c] = 0.0f;

    // lane-constant ldmatrix offsets (within a tile buffer)
    // A: row = mbase + ((lane>>3)&1)*8 + (lane&7), col halfs = (lane>>4)*8
    const int a_row = ((lane >> 3) & 1) * 8 + (lane & 7);
    const uint32_t a_off = (uint32_t)(mwarp * 32 + a_row) * ROWB + (lane >> 4) * 16;
    // B: row = n0 + ((lane>>4)<<3) + (lane&7), col halfs = ((lane>>3)&1)*8
    const int b_row = ((lane >> 4) << 3) + (lane & 7);
    const uint32_t b_off = (uint32_t)(nwarp * 64 + b_row) * ROWB + ((lane >> 3) & 1) * 16;

    // prologue: prefetch chunk 0 into stage 0
    load_chunk(sb + 0, sb + TILE_B, xtb, 0, tid);

    #pragma unroll
    for (int t = 0; t < NTAP; ++t) {
        const uint32_t cur = sb + (uint32_t)(t & 1) * STAGE_B;
        if (t < NTAP - 1) {
            const uint32_t nxt = sb + (uint32_t)((t + 1) & 1) * STAGE_B;
            load_chunk(nxt, nxt + TILE_B, xtb, t + 1, tid);
            cp_wait<1>();
        } else {
            cp_wait<0>();
        }
        __syncthreads();

        const uint32_t aB = cur + a_off;
        const uint32_t bB = cur + TILE_B + b_off;
        #pragma unroll
        for (int ks = 0; ks < 4; ++ks) {
            uint32_t a0[4], a1[4];
            ldm_x4(a0[0], a0[1], a0[2], a0[3], aB + ks * 32);
            ldm_x4(a1[0], a1[1], a1[2], a1[3], aB + 16 * ROWB + ks * 32);
            #pragma unroll
            for (int nf2 = 0; nf2 < 4; ++nf2) {
                uint32_t bb[4];
                ldm_x4(bb[0], bb[1], bb[2], bb[3], bB + nf2 * 16 * ROWB + ks * 32);
                mma16816(acc[0][nf2 * 2 + 0], a0[0], a0[1], a0[2], a0[3], bb[0], bb[1]);
                mma16816(acc[0][nf2 * 2 + 1], a0[0], a0[1], a0[2], a0[3], bb[2], bb[3]);
                mma16816(acc[1][nf2 * 2 + 0], a1[0], a1[1], a1[2], a1[3], bb[0], bb[1]);
                mma16816(acc[1][nf2 * 2 + 1], a1[0], a1[1], a1[2], a1[3], bb[2], bb[3]);
            }
        }
        __syncthreads();
    }

    // ---- epilogue: transpose through smem -> coalesced stores ----
    float* so = (float*)smem;   // [oc][136]
    #pragma unroll
    for (int mf = 0; mf < 2; ++mf)
        #pragma unroll
        for (int nf = 0; nf < 8; ++nf)
            #pragma unroll
            for (int c = 0; c < 4; ++c) {
                int oc = nwarp * 64 + nf * 8 + (lane & 3) * 2 + (c & 1);
                int m  = mwarp * 32 + mf * 16 + (lane >> 2) + (c & 2) * 4;
                so[oc * 136 + m] = acc[mf][nf][c];
            }
    __syncthreads();

    const int m_ = tid & 127;
    const int p  = m0 + m_;
    const int h  = p / PW;
    const int w_ = p % PW;
    const bool valid = (w_ < WW) && (h < HH);
    float* ob = out + ((size_t)b * C_OUT) * HH * WW + (size_t)h * WW + w_;
    const int oc_half = tid >> 7;   // 0 or 1
    #pragma unroll 8
    for (int j = 0; j < 64; ++j) {
        int oc = j * 2 + oc_half;
        if (valid)
            ob[(size_t)oc * HH * WW] = so[oc * 136 + m_] + __ldg(bias + oc);
    }
}

// ---------------- launch ----------------
extern "C" void kernel_launch(void* const* d_in, const int* in_sizes, int n_in,
                              void* d_out, int out_size) {
    const float* x    = (const float*)d_in[0];
    const float* wgt  = (const float*)d_in[1];
    const float* bias = (const float*)d_in[2];
    float* out = (float*)d_out;

    prep_weights<<<(NTAP * C_OUT * C_IN + 255) / 256, 256>>>(wgt);
    {
        dim3 g(PW, BATCH);
        prep_xt<<<g, 256>>>(x);
    }
    cudaFuncSetAttribute(oct_mma_kernel, cudaFuncAttributeMaxDynamicSharedMemorySize, SMEM_MAIN);
    {
        dim3 g(PW, BATCH);   // 130 m-tiles x 16 batches; N=128 per CTA
        oct_mma_kernel<<<g, 256, SMEM_MAIN>>>(bias, out);
    }
}

// round 4
// speedup vs baseline: 6.7375x; 1.0992x over previous
#include <cuda_runtime.h>
#include <cuda_fp16.h>
#include <cstdint>

// ---------------- problem constants ----------------
#define BATCH   16
#define C_IN    64
#define C_OUT   128
#define HH      128
#define WW      128
#define PW      130              // padded width/height
#define PIX_PAD (PW*PW)          // 16900 padded pixels
#define XT_ROWS 16904            // + guard rows (halo overrun)
#define NTAP    9

// ---- smem layout (dynamic) ----
// A: 392 rows x 144B (loaded once; taps are row-shifted views)
// B: 3-stage ring, each 128 rows x 144B
#define ROWB     144
#define A_ROWS   392
#define A_BYTES  (A_ROWS * ROWB)            // 56448
#define B_TILE   (128 * ROWB)               // 18432
#define NSTAGE   3
#define SMEM_B0  A_BYTES
#define SMEM_MAIN (A_BYTES + NSTAGE * B_TILE)   // 111744

// ---------------- device globals (scratch) ----------------
__device__ __half g_xt[(size_t)BATCH * XT_ROWS * C_IN];   // [b][pixel][ic]
__device__ __half g_wt[NTAP * C_OUT * C_IN];              // [tap][oc][ic]

// ---------------- ptx helpers ----------------
__device__ __forceinline__ uint32_t smem_u32(const void* p) {
    uint32_t a;
    asm("{ .reg .u64 t; cvta.to.shared.u64 t, %1; cvt.u32.u64 %0, t; }" : "=r"(a) : "l"(p));
    return a;
}
__device__ __forceinline__ void cp_async16(uint32_t dst, const void* src) {
    asm volatile("cp.async.cg.shared.global [%0], [%1], 16;" :: "r"(dst), "l"(src));
}
__device__ __forceinline__ void cp_commit() {
    asm volatile("cp.async.commit_group;" ::: "memory");
}
template <int N>
__device__ __forceinline__ void cp_wait() {
    asm volatile("cp.async.wait_group %0;" :: "n"(N) : "memory");
}
__device__ __forceinline__ void ldm_x4(uint32_t& r0, uint32_t& r1, uint32_t& r2, uint32_t& r3, uint32_t addr) {
    asm volatile("ldmatrix.sync.aligned.m8n8.x4.shared.b16 {%0,%1,%2,%3}, [%4];"
                 : "=r"(r0), "=r"(r1), "=r"(r2), "=r"(r3) : "r"(addr));
}
__device__ __forceinline__ void mma16816(float* c, uint32_t a0, uint32_t a1, uint32_t a2, uint32_t a3,
                                         uint32_t b0, uint32_t b1) {
    asm volatile("mma.sync.aligned.m16n8k16.row.col.f32.f16.f16.f32 "
                 "{%0,%1,%2,%3}, {%4,%5,%6,%7}, {%8,%9}, {%0,%1,%2,%3};"
                 : "+f"(c[0]), "+f"(c[1]), "+f"(c[2]), "+f"(c[3])
                 : "r"(a0), "r"(a1), "r"(a2), "r"(a3), "r"(b0), "r"(b1));
}

// ---------------- prep: weights fp32 -> fp16 [tap][oc][ic] ----------------
__global__ void prep_weights(const float* __restrict__ w) {
    int idx = blockIdx.x * 256 + threadIdx.x;
    if (idx >= NTAP * C_OUT * C_IN) return;
    int ic  = idx & 63;
    int oc  = (idx >> 6) & 127;
    int tap = idx >> 13;
    int i = oc >> 3, p = oc & 7;
    int j = ic >> 3, q = ic & 7;
    int kh = tap / 3, kw = tap % 3;
    g_wt[idx] = __float2half_rn(w[i * 4608 + j * 576 + p * 72 + q * 9 + kh * 3 + kw]);
}

// ---------------- prep: x fp32 NCHW -> padded pixel-major fp16 [b][pix][ic] ----------------
__global__ __launch_bounds__(256)
void prep_xt(const float* __restrict__ x) {
    __shared__ float buf[64][133];
    const int hp = blockIdx.x;   // 0..129
    const int b  = blockIdx.y;
    const int tid = threadIdx.x;
    __half* dst = g_xt + ((size_t)b * XT_ROWS + (size_t)hp * PW) * C_IN;

    if (hp == 0 || hp == PW - 1) {
        for (int idx = tid; idx < PW * C_IN; idx += 256) dst[idx] = __float2half_rn(0.0f);
        if (hp == PW - 1) {
            __half* g = g_xt + ((size_t)b * XT_ROWS + PIX_PAD) * C_IN;
            for (int idx = tid; idx < 4 * C_IN; idx += 256) g[idx] = __float2half_rn(0.0f);
        }
        return;
    }
    const float* src = x + ((size_t)b * C_IN * HH + (size_t)(hp - 1)) * WW;
    for (int idx = tid; idx < C_IN * 32; idx += 256) {
        int ic = idx >> 5, f4 = idx & 31;
        float4 v = *(const float4*)(src + (size_t)ic * HH * WW + f4 * 4);
        buf[ic][1 + f4 * 4 + 0] = v.x;
        buf[ic][1 + f4 * 4 + 1] = v.y;
        buf[ic][1 + f4 * 4 + 2] = v.z;
        buf[ic][1 + f4 * 4 + 3] = v.w;
    }
    __syncthreads();
    for (int idx = tid; idx < PW * C_IN; idx += 256) {
        int wp = idx >> 6, ic = idx & 63;
        float v = (wp == 0 || wp == PW - 1) ? 0.0f : buf[ic][wp];
        dst[(size_t)wp * C_IN + ic] = __float2half_rn(v);
    }
}

// ---------------- B-tap loader (cp.async, one commit group) ----------------
__device__ __forceinline__ void load_B(uint32_t sB, int tap, int tid) {
    const __half* bsrc = g_wt + (size_t)tap * C_OUT * C_IN;
    #pragma unroll
    for (int i = 0; i < 4; ++i) {
        int idx = tid + i * 256;
        int oc = idx >> 3, c = idx & 7;
        cp_async16(sB + oc * ROWB + c * 16, bsrc + (size_t)oc * C_IN + c * 8);
    }
    cp_commit();
}

// ---------------- main kernel ----------------
__global__ __launch_bounds__(256, 2)
void oct_mma_kernel(const float* __restrict__ bias, float* __restrict__ out) {
    extern __shared__ char smem[];
    const uint32_t sb = smem_u32(smem);
    const int tid  = threadIdx.x;
    const int wid  = tid >> 5;
    const int lane = tid & 31;
    const int mwarp = wid & 3;        // m block of 32
    const int nwarp = wid >> 2;       // n block of 64

    const int mtile = blockIdx.x;     // 0..129
    const int b     = blockIdx.y;     // 0..15
    const int m0    = mtile * 128;

    const __half* xtb = g_xt + ((size_t)b * XT_ROWS + m0) * C_IN;

    // ---- group 0: A rows (once) ----
    for (int idx = tid; idx < A_ROWS * 8; idx += 256) {
        int m = idx >> 3, c = idx & 7;
        cp_async16(sb + m * ROWB + c * 16, xtb + (size_t)m * C_IN + c * 8);
    }
    cp_commit();
    // ---- groups 1,2: B taps 0,1 ----
    load_B(sb + SMEM_B0 + 0 * B_TILE, 0, tid);
    load_B(sb + SMEM_B0 + 1 * B_TILE, 1, tid);

    float acc[2][8][4];
    #pragma unroll
    for (int mf = 0; mf < 2; ++mf)
        #pragma unroll
        for (int nf = 0; nf < 8; ++nf)
            #pragma unroll
            for (int c = 0; c < 4; ++c) acc[mf][nf][c] = 0.0f;

    // lane-constant ldmatrix offsets
    const int a_row = ((lane >> 3) & 1) * 8 + (lane & 7);
    const uint32_t a_off = (uint32_t)(mwarp * 32 + a_row) * ROWB + (lane >> 4) * 16;
    const int b_row = ((lane >> 4) << 3) + (lane & 7);
    const uint32_t b_off = (uint32_t)(nwarp * 64 + b_row) * ROWB + ((lane >> 3) & 1) * 16;

    const int shifts[NTAP] = {0, 1, 2, PW, PW + 1, PW + 2, 2 * PW, 2 * PW + 1, 2 * PW + 2};

    #pragma unroll
    for (int t = 0; t < NTAP; ++t) {
        if (t + 2 < NTAP) {
            load_B(sb + SMEM_B0 + (uint32_t)((t + 2) % NSTAGE) * B_TILE, t + 2, tid);
            cp_wait<2>();
        } else if (t + 2 == NTAP) {
            cp_wait<1>();
        } else {
            cp_wait<0>();
        }
        __syncthreads();

        const uint32_t aB = sb + a_off + (uint32_t)shifts[t] * ROWB;
        const uint32_t bB = sb + SMEM_B0 + (uint32_t)(t % NSTAGE) * B_TILE + b_off;
        #pragma unroll
        for (int ks = 0; ks < 4; ++ks) {
            uint32_t a0[4], a1[4];
            ldm_x4(a0[0], a0[1], a0[2], a0[3], aB + ks * 32);
            ldm_x4(a1[0], a1[1], a1[2], a1[3], aB + 16 * ROWB + ks * 32);
            #pragma unroll
            for (int nf2 = 0; nf2 < 4; ++nf2) {
                uint32_t bb[4];
                ldm_x4(bb[0], bb[1], bb[2], bb[3], bB + nf2 * 16 * ROWB + ks * 32);
                mma16816(acc[0][nf2 * 2 + 0], a0[0], a0[1], a0[2], a0[3], bb[0], bb[1]);
                mma16816(acc[0][nf2 * 2 + 1], a0[0], a0[1], a0[2], a0[3], bb[2], bb[3]);
                mma16816(acc[1][nf2 * 2 + 0], a1[0], a1[1], a1[2], a1[3], bb[0], bb[1]);
                mma16816(acc[1][nf2 * 2 + 1], a1[0], a1[1], a1[2], a1[3], bb[2], bb[3]);
            }
        }
        __syncthreads();
    }

    // ---- epilogue: transpose through smem -> coalesced stores ----
    float* so = (float*)smem;   // [oc][136]
    #pragma unroll
    for (int mf = 0; mf < 2; ++mf)
        #pragma unroll
        for (int nf = 0; nf < 8; ++nf)
            #pragma unroll
            for (int c = 0; c < 4; ++c) {
                int oc = nwarp * 64 + nf * 8 + (lane & 3) * 2 + (c & 1);
                int m  = mwarp * 32 + mf * 16 + (lane >> 2) + (c & 2) * 4;
                so[oc * 136 + m] = acc[mf][nf][c];
            }
    __syncthreads();

    const int m_ = tid & 127;
    const int p  = m0 + m_;
    const int h  = p / PW;
    const int w_ = p % PW;
    const bool valid = (w_ < WW) && (h < HH);
    float* ob = out + ((size_t)b * C_OUT) * HH * WW + (size_t)h * WW + w_;
    const int oc_half = tid >> 7;   // 0 or 1
    #pragma unroll 8
    for (int j = 0; j < 64; ++j) {
        int oc = j * 2 + oc_half;
        if (valid)
            ob[(size_t)oc * HH * WW] = so[oc * 136 + m_] + __ldg(bias + oc);
    }
}

// ---------------- launch ----------------
extern "C" void kernel_launch(void* const* d_in, const int* in_sizes, int n_in,
                              void* d_out, int out_size) {
    const float* x    = (const float*)d_in[0];
    const float* wgt  = (const float*)d_in[1];
    const float* bias = (const float*)d_in[2];
    float* out = (float*)d_out;

    prep_weights<<<(NTAP * C_OUT * C_IN + 255) / 256, 256>>>(wgt);
    {
        dim3 g(PW, BATCH);
        prep_xt<<<g, 256>>>(x);
    }
    cudaFuncSetAttribute(oct_mma_kernel, cudaFuncAttributeMaxDynamicSharedMemorySize, SMEM_MAIN);
    {
        dim3 g(PW, BATCH);   // 130 m-tiles x 16 batches; N=128 per CTA
        oct_mma_kernel<<<g, 256, SMEM_MAIN>>>(bias, out);
    }
}

// round 5
// speedup vs baseline: 7.1665x; 1.0637x over previous
#include <cuda_runtime.h>
#include <cuda_fp16.h>
#include <cstdint>

// ---------------- problem constants ----------------
#define BATCH   16
#define C_IN    64
#define C_OUT   128
#define HH      128
#define WW      128
#define PW      130              // padded width/height
#define PIX_PAD (PW*PW)          // 16900 padded pixels
#define XT_ROWS 16904            // + guard rows (halo overrun)
#define NTAP    9

// ---- smem layout (dynamic) ----
#define ROWB     144
#define A_ROWS   392
#define A_BYTES  (A_ROWS * ROWB)            // 56448
#define B_TILE   (128 * ROWB)               // 18432
#define NSTAGE   3
#define SMEM_B0  A_BYTES
#define SMEM_MAIN (A_BYTES + NSTAGE * B_TILE)   // 111744

// ---------------- device globals (scratch) ----------------
__device__ __half g_xt[(size_t)BATCH * XT_ROWS * C_IN];   // [b][pixel][ic]
__device__ __half g_wt[NTAP * C_OUT * C_IN];              // [tap][oc][ic]

// ---------------- ptx helpers ----------------
__device__ __forceinline__ uint32_t smem_u32(const void* p) {
    uint32_t a;
    asm("{ .reg .u64 t; cvta.to.shared.u64 t, %1; cvt.u32.u64 %0, t; }" : "=r"(a) : "l"(p));
    return a;
}
__device__ __forceinline__ void cp_async16(uint32_t dst, const void* src) {
    asm volatile("cp.async.cg.shared.global [%0], [%1], 16;" :: "r"(dst), "l"(src));
}
__device__ __forceinline__ void cp_commit() {
    asm volatile("cp.async.commit_group;" ::: "memory");
}
template <int N>
__device__ __forceinline__ void cp_wait() {
    asm volatile("cp.async.wait_group %0;" :: "n"(N) : "memory");
}
__device__ __forceinline__ void ldm_x4(uint32_t& r0, uint32_t& r1, uint32_t& r2, uint32_t& r3, uint32_t addr) {
    asm volatile("ldmatrix.sync.aligned.m8n8.x4.shared.b16 {%0,%1,%2,%3}, [%4];"
                 : "=r"(r0), "=r"(r1), "=r"(r2), "=r"(r3) : "r"(addr));
}
__device__ __forceinline__ void mma16816(float* c, uint32_t a0, uint32_t a1, uint32_t a2, uint32_t a3,
                                         uint32_t b0, uint32_t b1) {
    asm volatile("mma.sync.aligned.m16n8k16.row.col.f32.f16.f16.f32 "
                 "{%0,%1,%2,%3}, {%4,%5,%6,%7}, {%8,%9}, {%0,%1,%2,%3};"
                 : "+f"(c[0]), "+f"(c[1]), "+f"(c[2]), "+f"(c[3])
                 : "r"(a0), "r"(a1), "r"(a2), "r"(a3), "r"(b0), "r"(b1));
}

// ---------------- fused prep: weights + x transform ----------------
// grid (PW, BATCH+1): blockIdx.y == BATCH -> weight repack rows
__global__ __launch_bounds__(256)
void prep_fused(const float* __restrict__ x, const float* __restrict__ w) {
    __shared__ float buf[64][133];
    const int tid = threadIdx.x;

    if (blockIdx.y == BATCH) {
        // ---- weights fp32 -> fp16 [tap][oc][ic] ----
        for (int idx = blockIdx.x * 256 + tid; idx < NTAP * C_OUT * C_IN; idx += PW * 256) {
            int ic  = idx & 63;
            int oc  = (idx >> 6) & 127;
            int tap = idx >> 13;
            int i = oc >> 3, p = oc & 7;
            int j = ic >> 3, q = ic & 7;
            int kh = tap / 3, kw = tap % 3;
            g_wt[idx] = __float2half_rn(w[i * 4608 + j * 576 + p * 72 + q * 9 + kh * 3 + kw]);
        }
        return;
    }

    const int hp = blockIdx.x;   // 0..129
    const int b  = blockIdx.y;
    __half* dst = g_xt + ((size_t)b * XT_ROWS + (size_t)hp * PW) * C_IN;

    if (hp == 0 || hp == PW - 1) {
        // border rows: vectorized zeros (PW*64 halfs = 1040 uint4)
        uint4 z = make_uint4(0, 0, 0, 0);
        for (int idx = tid; idx < PW * C_IN / 8; idx += 256) ((uint4*)dst)[idx] = z;
        if (hp == PW - 1) {
            uint4* g = (uint4*)(g_xt + ((size_t)b * XT_ROWS + PIX_PAD) * C_IN);
            for (int idx = tid; idx < 4 * C_IN / 8; idx += 256) g[idx] = z;
        }
        return;
    }
    // load 64 ic rows of 128 floats (coalesced float4)
    const float* src = x + ((size_t)b * C_IN * HH + (size_t)(hp - 1)) * WW;
    for (int idx = tid; idx < C_IN * 32; idx += 256) {
        int ic = idx >> 5, f4 = idx & 31;
        float4 v = *(const float4*)(src + (size_t)ic * HH * WW + f4 * 4);
        buf[ic][1 + f4 * 4 + 0] = v.x;
        buf[ic][1 + f4 * 4 + 1] = v.y;
        buf[ic][1 + f4 * 4 + 2] = v.z;
        buf[ic][1 + f4 * 4 + 3] = v.w;
    }
    __syncthreads();
    // transposed write, half2 (4B) stores: per pixel 64 ic contiguous
    __half2* d2 = (__half2*)dst;
    for (int idx = tid; idx < PW * 32; idx += 256) {
        int wp = idx >> 5, icp = idx & 31;
        float v0 = 0.0f, v1 = 0.0f;
        if (wp != 0 && wp != PW - 1) {
            v0 = buf[icp * 2 + 0][wp];
            v1 = buf[icp * 2 + 1][wp];
        }
        d2[(size_t)wp * 32 + icp] = __floats2half2_rn(v0, v1);
    }
}

// ---------------- B-tap loader (cp.async, one commit group) ----------------
__device__ __forceinline__ void load_B(uint32_t sB, int tap, int tid) {
    const __half* bsrc = g_wt + (size_t)tap * C_OUT * C_IN;
    #pragma unroll
    for (int i = 0; i < 4; ++i) {
        int idx = tid + i * 256;
        int oc = idx >> 3, c = idx & 7;
        cp_async16(sB + oc * ROWB + c * 16, bsrc + (size_t)oc * C_IN + c * 8);
    }
    cp_commit();
}

// ---------------- main kernel ----------------
__global__ __launch_bounds__(256, 2)
void oct_mma_kernel(const float* __restrict__ bias, float* __restrict__ out) {
    extern __shared__ char smem[];
    __shared__ float bias_s[C_OUT];
    const uint32_t sb = smem_u32(smem);
    const int tid  = threadIdx.x;
    const int wid  = tid >> 5;
    const int lane = tid & 31;
    const int mwarp = wid & 3;        // m block of 32
    const int nwarp = wid >> 2;       // n block of 64

    const int mtile = blockIdx.x;     // 0..129
    const int b     = blockIdx.y;     // 0..15
    const int m0    = mtile * 128;

    const __half* xtb = g_xt + ((size_t)b * XT_ROWS + m0) * C_IN;

    if (tid < C_OUT) bias_s[tid] = bias[tid];

    // ---- group 0: A rows (once) ----
    for (int idx = tid; idx < A_ROWS * 8; idx += 256) {
        int m = idx >> 3, c = idx & 7;
        cp_async16(sb + m * ROWB + c * 16, xtb + (size_t)m * C_IN + c * 8);
    }
    cp_commit();
    // ---- groups 1,2: B taps 0,1 ----
    load_B(sb + SMEM_B0 + 0 * B_TILE, 0, tid);
    load_B(sb + SMEM_B0 + 1 * B_TILE, 1, tid);

    float acc[2][8][4];
    #pragma unroll
    for (int mf = 0; mf < 2; ++mf)
        #pragma unroll
        for (int nf = 0; nf < 8; ++nf)
            #pragma unroll
            for (int c = 0; c < 4; ++c) acc[mf][nf][c] = 0.0f;

    // lane-constant ldmatrix offsets
    const int a_row = ((lane >> 3) & 1) * 8 + (lane & 7);
    const uint32_t a_off = (uint32_t)(mwarp * 32 + a_row) * ROWB + (lane >> 4) * 16;
    const int b_row = ((lane >> 4) << 3) + (lane & 7);
    const uint32_t b_off = (uint32_t)(nwarp * 64 + b_row) * ROWB + ((lane >> 3) & 1) * 16;

    const int shifts[NTAP] = {0, 1, 2, PW, PW + 1, PW + 2, 2 * PW, 2 * PW + 1, 2 * PW + 2};

    // Single sync per tap:
    //   wait B(t) ready -> sync -> issue load B(t+2) (slot last read at tap t-1,
    //   all warps past that compute due to this sync) -> compute tap t
    #pragma unroll
    for (int t = 0; t < NTAP; ++t) {
        if (t < NTAP - 1) cp_wait<1>(); else cp_wait<0>();
        __syncthreads();
        if (t + 2 < NTAP)
            load_B(sb + SMEM_B0 + (uint32_t)((t + 2) % NSTAGE) * B_TILE, t + 2, tid);

        const uint32_t aB = sb + a_off + (uint32_t)shifts[t] * ROWB;
        const uint32_t bB = sb + SMEM_B0 + (uint32_t)(t % NSTAGE) * B_TILE + b_off;
        #pragma unroll
        for (int ks = 0; ks < 4; ++ks) {
            uint32_t a0[4], a1[4];
            ldm_x4(a0[0], a0[1], a0[2], a0[3], aB + ks * 32);
            ldm_x4(a1[0], a1[1], a1[2], a1[3], aB + 16 * ROWB + ks * 32);
            #pragma unroll
            for (int nf2 = 0; nf2 < 4; ++nf2) {
                uint32_t bb[4];
                ldm_x4(bb[0], bb[1], bb[2], bb[3], bB + nf2 * 16 * ROWB + ks * 32);
                mma16816(acc[0][nf2 * 2 + 0], a0[0], a0[1], a0[2], a0[3], bb[0], bb[1]);
                mma16816(acc[0][nf2 * 2 + 1], a0[0], a0[1], a0[2], a0[3], bb[2], bb[3]);
                mma16816(acc[1][nf2 * 2 + 0], a1[0], a1[1], a1[2], a1[3], bb[0], bb[1]);
                mma16816(acc[1][nf2 * 2 + 1], a1[0], a1[1], a1[2], a1[3], bb[2], bb[3]);
            }
        }
    }
    __syncthreads();   // protect smem reuse by epilogue

    // ---- epilogue: transpose (bias folded) through smem -> coalesced stores ----
    float* so = (float*)smem;   // [oc][136]
    #pragma unroll
    for (int mf = 0; mf < 2; ++mf)
        #pragma unroll
        for (int nf = 0; nf < 8; ++nf)
            #pragma unroll
            for (int c = 0; c < 4; ++c) {
                int oc = nwarp * 64 + nf * 8 + (lane & 3) * 2 + (c & 1);
                int m  = mwarp * 32 + mf * 16 + (lane >> 2) + (c & 2) * 4;
                so[oc * 136 + m] = acc[mf][nf][c] + bias_s[oc];
            }
    __syncthreads();

    const int m_ = tid & 127;
    const int p  = m0 + m_;
    const int h  = p / PW;
    const int w_ = p % PW;
    const int oc_half = tid >> 7;   // 0 or 1
    if ((w_ < WW) && (h < HH)) {
        float* ob = out + ((size_t)b * C_OUT) * HH * WW + (size_t)h * WW + w_;
        #pragma unroll 8
        for (int j = 0; j < 64; ++j) {
            int oc = j * 2 + oc_half;
            ob[(size_t)oc * HH * WW] = so[oc * 136 + m_];
        }
    }
}

// ---------------- launch ----------------
extern "C" void kernel_launch(void* const* d_in, const int* in_sizes, int n_in,
                              void* d_out, int out_size) {
    const float* x    = (const float*)d_in[0];
    const float* wgt  = (const float*)d_in[1];
    const float* bias = (const float*)d_in[2];
    float* out = (float*)d_out;

    {
        dim3 g(PW, BATCH + 1);          // y==BATCH rows do weight repack
        prep_fused<<<g, 256>>>(x, wgt);
    }
    cudaFuncSetAttribute(oct_mma_kernel, cudaFuncAttributeMaxDynamicSharedMemorySize, SMEM_MAIN);
    {
        dim3 g(PW, BATCH);              // 130 m-tiles x 16 batches; N=128 per CTA
        oct_mma_kernel<<<g, 256, SMEM_MAIN>>>(bias, out);
    }
}